// round 7
// baseline (speedup 1.0000x reference)
#include <cuda_runtime.h>
#include <cuda_fp16.h>
#include <cstdint>

// x (2,4,128,128,128) f32, y (2,1,128,128,128) int32 -> scalar f32
#define SPB    (1u << 21)       // 128^3 voxels per batch
#define NTOT   (1u << 22)       // 2 * 128^3
#define NWORDS (NTOT / 32)      // packed words (32 voxels each): 131072

// Bit-plane scratch, interleaved: .x = A-plane (P==1), .y = B-plane (P in {0,3})
// crit = (rA & dil3D(B)) | (rB & dil3D(A))
__device__ uint2 g_rAB[NWORDS];     // raw planes
__device__ uint2 g_dAB[NWORDS];     // x-dilated planes
__device__ uint4 g_ceh[NTOT / 8];   // per-voxel CE, fp16 (8 halves per uint4)

// ---------------------------------------------------------------------------
// K1: argmax -> bit planes (+x-dilation), CE (fp16). 4 voxels/thread.
// Block = 256 threads = 1024 voxels = 8 complete x-rows = 32 packed words.
// ---------------------------------------------------------------------------
__global__ void k1(const float* __restrict__ x,
                   const int*   __restrict__ y,
                   float* __restrict__ out) {
    __shared__ unsigned char snib[256];   // lo nibble: A bits, hi nibble: B bits

    unsigned t  = blockIdx.x * 256u + threadIdx.x;
    unsigned i4 = t * 4u;
    unsigned b  = i4 >> 21;
    unsigned v  = i4 & (SPB - 1);
    const float* xb = x + (size_t)b * 4 * SPB + v;

    float4 a0 = *(const float4*)(xb);
    float4 a1 = *(const float4*)(xb + SPB);
    float4 a2 = *(const float4*)(xb + 2 * SPB);
    float4 a3 = *(const float4*)(xb + 3 * SPB);
    int4   yy = *(const int4*)(y + i4);

    float c0[4] = {a0.x, a0.y, a0.z, a0.w};
    float c1[4] = {a1.x, a1.y, a1.z, a1.w};
    float c2[4] = {a2.x, a2.y, a2.z, a2.w};
    float c3[4] = {a3.x, a3.y, a3.z, a3.w};
    int   yv[4] = {yy.x, yy.y, yy.z, yy.w};

    unsigned nib = 0;
    float cef[4];
    #pragma unroll
    for (int j = 0; j < 4; j++) {
        float x0 = c0[j], x1 = c1[j], x2 = c2[j], x3 = c3[j];
        float best = x0; int p = 0;
        if (x1 > best) { best = x1; p = 1; }
        if (x2 > best) { best = x2; p = 2; }
        if (x3 > best) { best = x3; p = 3; }
        unsigned A = (p == 1) ? 1u : 0u;
        unsigned B = (p == 0 || p == 3) ? 1u : 0u;
        nib |= (A << j) | (B << (j + 4));
        float m = best;
        float lse = m + __logf(__expf(x0 - m) + __expf(x1 - m) +
                               __expf(x2 - m) + __expf(x3 - m));
        int yi = yv[j];
        float xy = (yi == 0) ? x0 : (yi == 1) ? x1 : (yi == 2) ? x2 : x3;
        cef[j] = lse - xy;
    }

    // fp16 CE, 4 halves = 8 bytes per thread
    __half2 h01 = __floats2half2_rn(cef[0], cef[1]);
    __half2 h23 = __floats2half2_rn(cef[2], cef[3]);
    uint2 cw;
    cw.x = *(const unsigned*)&h01;
    cw.y = *(const unsigned*)&h23;
    ((uint2*)g_ceh)[t] = cw;

    snib[threadIdx.x] = (unsigned char)nib;
    __syncthreads();

    // Warp 0 assembles 32 words (one per lane), x-dilates, writes planes.
    if (threadIdx.x < 32) {
        unsigned w = threadIdx.x;
        uint32_t wA = 0, wB = 0;
        #pragma unroll
        for (int j = 0; j < 8; j++) {
            unsigned n = snib[w * 8 + j];
            wA |= (n & 0xFu) << (4 * j);
            wB |= (n >> 4)   << (4 * j);
        }
        // neighbor words live in adjacent lanes; clamp at row edges (4 words/row)
        uint32_t pA  = __shfl_up_sync(0xFFFFFFFFu, wA, 1);
        uint32_t nAx = __shfl_down_sync(0xFFFFFFFFu, wA, 1);
        uint32_t pB  = __shfl_up_sync(0xFFFFFFFFu, wB, 1);
        uint32_t nBx = __shfl_down_sync(0xFFFFFFFFu, wB, 1);
        if ((w & 3u) == 0) { pA = 0; pB = 0; }
        if ((w & 3u) == 3) { nAx = 0; nBx = 0; }
        uint32_t dA = wA | (wA << 1) | (pA >> 31) | (wA >> 1) | (nAx << 31);
        uint32_t dB = wB | (wB << 1) | (pB >> 31) | (wB >> 1) | (nBx << 31);

        unsigned gw = blockIdx.x * 32u + w;
        g_rAB[gw] = make_uint2(wA, wB);
        g_dAB[gw] = make_uint2(dA, dB);
    }

    if (t == 0) out[0] = 0.0f;
}

// ---------------------------------------------------------------------------
// K2: 9-tap (y,z) OR over x-dilated planes -> crit word -> masked CE sum.
// One packed word (32 voxels) per thread; 128-thread blocks (grid 1024).
// word layout: b(1) | z(7) | y(7) | wx(2)
// CE is prefetched unconditionally (crit ~75% dense) to overlap with taps.
// ---------------------------------------------------------------------------
__global__ void k2(float* __restrict__ out) {
    unsigned wi = blockIdx.x * 128u + threadIdx.x;   // < NWORDS
    unsigned yr = (wi >> 2) & 127u;
    unsigned z  = (wi >> 9) & 127u;

    // prefetch CE (4x uint4 = 64B) — independent of the taps
    const uint4* cep = &g_ceh[wi * 4u];
    uint4 cq0 = cep[0], cq1 = cep[1], cq2 = cep[2], cq3 = cep[3];
    uint2 r = g_rAB[wi];

    uint32_t nA = 0, nB = 0;
    #pragma unroll
    for (int dz = -1; dz <= 1; dz++) {
        if ((dz == -1 && z == 0) || (dz == 1 && z == 127)) continue;
        #pragma unroll
        for (int dy = -1; dy <= 1; dy++) {
            if ((dy == -1 && yr == 0) || (dy == 1 && yr == 127)) continue;
            uint2 u = g_dAB[(int)wi + dz * 512 + dy * 4];
            nA |= u.x; nB |= u.y;
        }
    }

    uint32_t crit = (r.x & nB) | (r.y & nA);

    float s = 0.0f;
    {
        unsigned hw[8] = {cq0.x, cq0.y, cq0.z, cq0.w, cq1.x, cq1.y, cq1.z, cq1.w};
        unsigned hw2[8] = {cq2.x, cq2.y, cq2.z, cq2.w, cq3.x, cq3.y, cq3.z, cq3.w};
        #pragma unroll
        for (int j = 0; j < 8; j++) {
            float2 f2 = __half22float2(*(const __half2*)&hw[j]);
            if (crit & (1u << (2 * j)))     s += f2.x;
            if (crit & (2u << (2 * j)))     s += f2.y;
        }
        #pragma unroll
        for (int j = 0; j < 8; j++) {
            float2 f2 = __half22float2(*(const __half2*)&hw2[j]);
            if (crit & (1u << (16 + 2 * j))) s += f2.x;
            if (crit & (2u << (16 + 2 * j))) s += f2.y;
        }
    }

    // block reduce (4 warps) + atomic
    #pragma unroll
    for (int o = 16; o; o >>= 1) s += __shfl_down_sync(0xFFFFFFFFu, s, o);
    __shared__ float ws[4];
    int lane = threadIdx.x & 31, warp = threadIdx.x >> 5;
    if (lane == 0) ws[warp] = s;
    __syncthreads();
    if (warp == 0) {
        s = (lane < 4) ? ws[lane] : 0.0f;
        #pragma unroll
        for (int o = 2; o; o >>= 1) s += __shfl_down_sync(0xFFFFFFFFu, s, o);
        if (lane == 0) atomicAdd(out, 0.5f * s);   // mean over batch of 2
    }
}

// ---------------------------------------------------------------------------
extern "C" void kernel_launch(void* const* d_in, const int* in_sizes, int n_in,
                              void* d_out, int out_size) {
    const float* x = (const float*)d_in[0];
    const int*   y = (const int*)d_in[1];
    float* out = (float*)d_out;

    k1<<<NTOT / 1024, 256>>>(x, y, out);
    k2<<<NWORDS / 128, 128>>>(out);
}

// round 8
// speedup vs baseline: 1.0017x; 1.0017x over previous
#include <cuda_runtime.h>
#include <cuda_fp16.h>
#include <cstdint>

// x (2,4,128,128,128) f32, y (2,1,128,128,128) int32 -> scalar f32
#define SPB    (1u << 21)       // 128^3 voxels per batch
#define NTOT   (1u << 22)       // 2 * 128^3
#define NWORDS (NTOT / 32)      // packed words (32 voxels each): 131072

// Bit-plane scratch, interleaved: .x = A-plane (P==1), .y = B-plane (P in {0,3})
// crit = (rA & dil3D(B)) | (rB & dil3D(A))
__device__ uint2 g_rAB[NWORDS];     // raw planes
__device__ uint2 g_dAB[NWORDS];     // x-dilated planes
__device__ uint4 g_ceh[NTOT / 8];   // per-voxel CE, fp16 (8 halves per uint4)

// ---------------------------------------------------------------------------
// K1: argmax -> bit planes (+x-dilation), CE (fp16). 4 voxels/thread.
// Block = 256 threads = 1024 voxels = 8 complete x-rows = 32 packed words.
// ---------------------------------------------------------------------------
__global__ void k1(const float* __restrict__ x,
                   const int*   __restrict__ y,
                   float* __restrict__ out) {
    __shared__ unsigned char snib[256];   // lo nibble: A bits, hi nibble: B bits

    unsigned t  = blockIdx.x * 256u + threadIdx.x;
    unsigned i4 = t * 4u;
    unsigned b  = i4 >> 21;
    unsigned v  = i4 & (SPB - 1);
    const float* xb = x + (size_t)b * 4 * SPB + v;

    float4 a0 = *(const float4*)(xb);
    float4 a1 = *(const float4*)(xb + SPB);
    float4 a2 = *(const float4*)(xb + 2 * SPB);
    float4 a3 = *(const float4*)(xb + 3 * SPB);
    int4   yy = *(const int4*)(y + i4);

    float c0[4] = {a0.x, a0.y, a0.z, a0.w};
    float c1[4] = {a1.x, a1.y, a1.z, a1.w};
    float c2[4] = {a2.x, a2.y, a2.z, a2.w};
    float c3[4] = {a3.x, a3.y, a3.z, a3.w};
    int   yv[4] = {yy.x, yy.y, yy.z, yy.w};

    unsigned nib = 0;
    float cef[4];
    #pragma unroll
    for (int j = 0; j < 4; j++) {
        float x0 = c0[j], x1 = c1[j], x2 = c2[j], x3 = c3[j];
        float best = x0; int p = 0;
        if (x1 > best) { best = x1; p = 1; }
        if (x2 > best) { best = x2; p = 2; }
        if (x3 > best) { best = x3; p = 3; }
        unsigned A = (p == 1) ? 1u : 0u;
        unsigned B = (p == 0 || p == 3) ? 1u : 0u;
        nib |= (A << j) | (B << (j + 4));
        float m = best;
        float lse = m + __logf(__expf(x0 - m) + __expf(x1 - m) +
                               __expf(x2 - m) + __expf(x3 - m));
        int yi = yv[j];
        float xy = (yi == 0) ? x0 : (yi == 1) ? x1 : (yi == 2) ? x2 : x3;
        cef[j] = lse - xy;
    }

    // fp16 CE, 4 halves = 8 bytes per thread
    __half2 h01 = __floats2half2_rn(cef[0], cef[1]);
    __half2 h23 = __floats2half2_rn(cef[2], cef[3]);
    uint2 cw;
    cw.x = *(const unsigned*)&h01;
    cw.y = *(const unsigned*)&h23;
    ((uint2*)g_ceh)[t] = cw;

    snib[threadIdx.x] = (unsigned char)nib;
    __syncthreads();

    // Warp 0 assembles 32 words (one per lane), x-dilates, writes planes.
    if (threadIdx.x < 32) {
        unsigned w = threadIdx.x;
        uint32_t wA = 0, wB = 0;
        #pragma unroll
        for (int j = 0; j < 8; j++) {
            unsigned n = snib[w * 8 + j];
            wA |= (n & 0xFu) << (4 * j);
            wB |= (n >> 4)   << (4 * j);
        }
        // neighbor words live in adjacent lanes; clamp at row edges (4 words/row)
        uint32_t pA  = __shfl_up_sync(0xFFFFFFFFu, wA, 1);
        uint32_t nAx = __shfl_down_sync(0xFFFFFFFFu, wA, 1);
        uint32_t pB  = __shfl_up_sync(0xFFFFFFFFu, wB, 1);
        uint32_t nBx = __shfl_down_sync(0xFFFFFFFFu, wB, 1);
        if ((w & 3u) == 0) { pA = 0; pB = 0; }
        if ((w & 3u) == 3) { nAx = 0; nBx = 0; }
        uint32_t dA = wA | (wA << 1) | (pA >> 31) | (wA >> 1) | (nAx << 31);
        uint32_t dB = wB | (wB << 1) | (pB >> 31) | (wB >> 1) | (nBx << 31);

        unsigned gw = blockIdx.x * 32u + w;
        g_rAB[gw] = make_uint2(wA, wB);
        g_dAB[gw] = make_uint2(dA, dB);
    }

    if (t == 0) out[0] = 0.0f;
}

// ---------------------------------------------------------------------------
// K2: 9-tap (y,z) OR over x-dilated planes -> crit word -> masked CE sum.
// One packed word (32 voxels) per thread; 128-thread blocks (grid 1024).
// word layout: b(1) | z(7) | y(7) | wx(2)
// CE is prefetched unconditionally (crit ~75% dense) to overlap with taps.
// ---------------------------------------------------------------------------
__global__ void k2(float* __restrict__ out) {
    unsigned wi = blockIdx.x * 128u + threadIdx.x;   // < NWORDS
    unsigned yr = (wi >> 2) & 127u;
    unsigned z  = (wi >> 9) & 127u;

    // prefetch CE (4x uint4 = 64B) — independent of the taps
    const uint4* cep = &g_ceh[wi * 4u];
    uint4 cq0 = cep[0], cq1 = cep[1], cq2 = cep[2], cq3 = cep[3];
    uint2 r = g_rAB[wi];

    uint32_t nA = 0, nB = 0;
    #pragma unroll
    for (int dz = -1; dz <= 1; dz++) {
        if ((dz == -1 && z == 0) || (dz == 1 && z == 127)) continue;
        #pragma unroll
        for (int dy = -1; dy <= 1; dy++) {
            if ((dy == -1 && yr == 0) || (dy == 1 && yr == 127)) continue;
            uint2 u = g_dAB[(int)wi + dz * 512 + dy * 4];
            nA |= u.x; nB |= u.y;
        }
    }

    uint32_t crit = (r.x & nB) | (r.y & nA);

    float s = 0.0f;
    {
        unsigned hw[8] = {cq0.x, cq0.y, cq0.z, cq0.w, cq1.x, cq1.y, cq1.z, cq1.w};
        unsigned hw2[8] = {cq2.x, cq2.y, cq2.z, cq2.w, cq3.x, cq3.y, cq3.z, cq3.w};
        #pragma unroll
        for (int j = 0; j < 8; j++) {
            float2 f2 = __half22float2(*(const __half2*)&hw[j]);
            if (crit & (1u << (2 * j)))     s += f2.x;
            if (crit & (2u << (2 * j)))     s += f2.y;
        }
        #pragma unroll
        for (int j = 0; j < 8; j++) {
            float2 f2 = __half22float2(*(const __half2*)&hw2[j]);
            if (crit & (1u << (16 + 2 * j))) s += f2.x;
            if (crit & (2u << (16 + 2 * j))) s += f2.y;
        }
    }

    // block reduce (4 warps) + atomic
    #pragma unroll
    for (int o = 16; o; o >>= 1) s += __shfl_down_sync(0xFFFFFFFFu, s, o);
    __shared__ float ws[4];
    int lane = threadIdx.x & 31, warp = threadIdx.x >> 5;
    if (lane == 0) ws[warp] = s;
    __syncthreads();
    if (warp == 0) {
        s = (lane < 4) ? ws[lane] : 0.0f;
        #pragma unroll
        for (int o = 2; o; o >>= 1) s += __shfl_down_sync(0xFFFFFFFFu, s, o);
        if (lane == 0) atomicAdd(out, 0.5f * s);   // mean over batch of 2
    }
}

// ---------------------------------------------------------------------------
extern "C" void kernel_launch(void* const* d_in, const int* in_sizes, int n_in,
                              void* d_out, int out_size) {
    const float* x = (const float*)d_in[0];
    const int*   y = (const int*)d_in[1];
    float* out = (float*)d_out;

    k1<<<NTOT / 1024, 256>>>(x, y, out);
    k2<<<NWORDS / 128, 128>>>(out);
}